// round 15
// baseline (speedup 1.0000x reference)
#include <cuda_runtime.h>
#include <cuda_bf16.h>
#include <cuda_fp16.h>
#include <cstdint>
#include <math.h>

// Problem constants
#define TOK   8192      // B*L
#define HIDN  2048
#define PW    8192      // QKV (6144) + gate (2048)
#define LSEQ  2048

// ---------------------------------------------------------------------------
// Global scratch (allocation-free rule: device globals)
// ---------------------------------------------------------------------------
__device__ float   g_proj [(size_t)TOK * PW];    // 256 MB fp32
__device__ __half  g_hs_hi[(size_t)TOK * HIDN];  // activations fp16 2-split
__device__ __half  g_hs_lo[(size_t)TOK * HIDN];
__device__ __half  g_wq_hi[(size_t)PW  * HIDN];  // W_qkvg^T [N][K] fp16 single
__device__ __half  g_wo_hi[(size_t)HIDN* HIDN];  // W_out^T  [N][K] fp16 single
__device__ __half  g_at_hi[(size_t)TOK * HIDN];  // attention out fp16 2-split
__device__ __half  g_at_lo[(size_t)TOK * HIDN];
// head-major attention operands (bf16 x3 path)
__device__ __nv_bfloat16  g_q_hi[(size_t)64 * LSEQ * 128];
__device__ __nv_bfloat16  g_q_lo[(size_t)64 * LSEQ * 128];
__device__ __nv_bfloat16  g_k_hi[(size_t)64 * LSEQ * 128];
__device__ __nv_bfloat16  g_k_lo[(size_t)64 * LSEQ * 128];
__device__ __nv_bfloat16  g_v_hi[(size_t)64 * 128 * LSEQ];
__device__ __nv_bfloat16  g_v_lo[(size_t)64 * 128 * LSEQ];
// RoPE table
__device__ float g_ropec[LSEQ * 64];
__device__ float g_ropes[LSEQ * 64];

// ---------------------------------------------------------------------------
// Helpers
// ---------------------------------------------------------------------------
__device__ __forceinline__ uint32_t smem_to_u32(const void* smem_ptr) {
    uint32_t addr;
    asm("{ .reg .u64 tmp; cvta.to.shared.u64 tmp, %1; cvt.u32.u64 %0, tmp; }"
        : "=r"(addr) : "l"(smem_ptr));
    return addr;
}

#define SMEM_SWIZZLE_128B(byte_offset) \
    ((byte_offset) ^ ((((uint32_t)(byte_offset)) >> 3) & 0x70u))

#define CP_ASYNC_16(smem_u32, gptr) \
    asm volatile("cp.async.cg.shared.global [%0], [%1], 16;" \
                 :: "r"(smem_u32), "l"(gptr) : "memory")
#define CP_ASYNC_COMMIT() asm volatile("cp.async.commit_group;" ::: "memory")
#define CP_ASYNC_WAIT_1() asm volatile("cp.async.wait_group 1;" ::: "memory")
#define CP_ASYNC_WAIT_0() asm volatile("cp.async.wait_group 0;" ::: "memory")

#define LDSM_X4(r0, r1, r2, r3, addr) \
    asm volatile("ldmatrix.sync.aligned.m8n8.x4.shared.b16 {%0,%1,%2,%3}, [%4];" \
                 : "=r"(r0), "=r"(r1), "=r"(r2), "=r"(r3) : "r"(addr))

// bf16 MMA (attention)
#define MMA_16816(c, a, b) \
    asm volatile("mma.sync.aligned.m16n8k16.row.col.f32.bf16.bf16.f32 " \
                 "{%0,%1,%2,%3}, {%4,%5,%6,%7}, {%8,%9}, {%0,%1,%2,%3};" \
                 : "+f"((c)[0]), "+f"((c)[1]), "+f"((c)[2]), "+f"((c)[3]) \
                 : "r"((a)[0]), "r"((a)[1]), "r"((a)[2]), "r"((a)[3]), \
                   "r"((b)[0]), "r"((b)[1]))

// fp16 MMA (GEMMs)
#define MMA_F16(c, a, b) \
    asm volatile("mma.sync.aligned.m16n8k16.row.col.f32.f16.f16.f32 " \
                 "{%0,%1,%2,%3}, {%4,%5,%6,%7}, {%8,%9}, {%0,%1,%2,%3};" \
                 : "+f"((c)[0]), "+f"((c)[1]), "+f"((c)[2]), "+f"((c)[3]) \
                 : "r"((a)[0]), "r"((a)[1]), "r"((a)[2]), "r"((a)[3]), \
                   "r"((b)[0]), "r"((b)[1]))

// pack two fp32 -> bf16x2 (lower half = first arg)
#define PACK_BF16X2(res, flo, fhi) \
    asm("cvt.rn.bf16x2.f32 %0, %1, %2;" : "=r"(res) : "f"(fhi), "f"(flo))

// ---------------------------------------------------------------------------
// RoPE table (fp64 once)
// ---------------------------------------------------------------------------
__global__ void rope_kernel(float* __restrict__ cs, float* __restrict__ sn)
{
    const int i = threadIdx.x;     // 0..63
    const int l = blockIdx.x;      // 0..2047
    double f   = pow(10000.0, -(double)i / 64.0);
    double ang = (double)l * f;
    double s, c;
    sincos(ang, &s, &c);
    cs[l * 64 + i] = (float)c;
    sn[l * 64 + i] = (float)s;
}

// ---------------------------------------------------------------------------
// elementwise fp32 -> fp16 hi/lo split (activations)
// ---------------------------------------------------------------------------
__global__ __launch_bounds__(256) void split_kernel(const float* __restrict__ x,
                                                    __half* __restrict__ hi,
                                                    __half* __restrict__ lo, int n4)
{
    int i = blockIdx.x * 256 + threadIdx.x;
    if (i >= n4) return;
    float4 v = ((const float4*)x)[i];
    float vv[4];
    vv[0] = v.x; vv[1] = v.y; vv[2] = v.z; vv[3] = v.w;
    __half hbuf[4], lbuf[4];
    #pragma unroll
    for (int j = 0; j < 4; j++) {
        __half h = __float2half_rn(vv[j]);
        hbuf[j] = h;
        lbuf[j] = __float2half_rn(vv[j] - __half2float(h));
    }
    *(uint2*)&hi[(size_t)i * 4] = *(const uint2*)hbuf;
    *(uint2*)&lo[(size_t)i * 4] = *(const uint2*)lbuf;
}

// ---------------------------------------------------------------------------
// W [K][N] fp32 -> Wt_hi [N][K] fp16 (transpose)
// ---------------------------------------------------------------------------
__global__ __launch_bounds__(256) void tsplit_kernel(const float* __restrict__ W,
                                                     __half* __restrict__ hi,
                                                     int K, int N)
{
    __shared__ float t[32][33];
    const int bn = blockIdx.x * 32;
    const int bk = blockIdx.y * 32;
    const int x = threadIdx.x & 31;
    const int y4 = (threadIdx.x >> 5) * 4;
    #pragma unroll
    for (int r = 0; r < 4; r++)
        t[y4 + r][x] = W[(size_t)(bk + y4 + r) * N + bn + x];
    __syncthreads();
    #pragma unroll
    for (int r = 0; r < 4; r++)
        hi[(size_t)(bn + y4 + r) * K + bk + x] = __float2half_rn(t[x][y4 + r]);
}

// ---------------------------------------------------------------------------
// fp16 2-pass GEMM (round-13 config): C[M,N] = (Ah+Al)[M,K] @ Bh[N,K]^T.
// 128x128 CTA tile, 256 threads, BK=64, 2-stage cp.async, 96 KB smem.
// CTAs with bn >= n_full use a single (Ah only) pass — gate-column fast path.
// ---------------------------------------------------------------------------
#define GSM_TILE   16384
#define GSM_STAGE  (3 * GSM_TILE)        // Ah, Al, Bh
#define GSM_TOTAL  (2 * GSM_STAGE)       // 96 KB

__global__ __launch_bounds__(256, 2) void gemm_f16x2(
    const __half* __restrict__ Ahi, const __half* __restrict__ Alo,
    const __half* __restrict__ Bh,
    float* __restrict__ C, int M, int N, int K, int n_full)
{
    extern __shared__ char smc[];
    const uint32_t sb = smem_to_u32(smc);
    const int tid  = threadIdx.x;
    const int wid  = tid >> 5;
    const int lane = tid & 31;
    const int wm   = wid & 1;
    const int wn   = wid >> 1;
    const int bm   = blockIdx.y << 7;
    const int bn   = blockIdx.x << 7;
    const bool full = (bn < n_full);

    const int r0  = tid >> 3;
    const int c16 = tid & 7;

    const __half* srcs[3];
    srcs[0] = Ahi + (size_t)bm * K;
    srcs[1] = Alo + (size_t)bm * K;
    srcs[2] = Bh  + (size_t)bn * K;

    const int nc = K >> 6;

    auto issue_chunk = [&](int c, int buf) {
        const int k0 = c << 6;
        const uint32_t bufb = sb + buf * GSM_STAGE;
        #pragma unroll
        for (int t = 0; t < 3; t++) {
            if (t == 1 && !full) continue;
            const __half* s = srcs[t] + k0;
            #pragma unroll
            for (int rr = 0; rr < 4; rr++) {
                const int r = r0 + rr * 32;
                const uint32_t so = bufb + t * GSM_TILE +
                    SMEM_SWIZZLE_128B((uint32_t)(r * 128 + c16 * 16));
                CP_ASYNC_16(so, s + (size_t)r * K + c16 * 8);
            }
        }
    };

    float acc[4][4][4];
    #pragma unroll
    for (int mi = 0; mi < 4; mi++)
        #pragma unroll
        for (int ni = 0; ni < 4; ni++)
            #pragma unroll
            for (int j = 0; j < 4; j++) acc[mi][ni][j] = 0.f;

    const int lr   = lane & 7;
    const int a_row = lr + ((lane >> 3) & 1) * 8;
    const int a_kb  = ((lane >> 4) & 1) * 16;
    const int b_row = lr + ((lane >> 4) & 1) * 8;
    const int b_kb  = ((lane >> 3) & 1) * 16;

    issue_chunk(0, 0);
    CP_ASYNC_COMMIT();

    for (int c = 0; c < nc; c++) {
        const int buf = c & 1;
        if (c + 1 < nc) {
            issue_chunk(c + 1, buf ^ 1);
            CP_ASYNC_COMMIT();
            CP_ASYNC_WAIT_1();
        } else {
            CP_ASYNC_WAIT_0();
        }
        __syncthreads();

        const uint32_t Ab = sb + buf * GSM_STAGE;
        const uint32_t Bb = Ab + 2 * GSM_TILE;

        #pragma unroll
        for (int ks = 0; ks < 4; ks++) {
            uint32_t ah[4][4], al[4][4], bh[4][2];
            #pragma unroll
            for (int mi = 0; mi < 4; mi++) {
                const uint32_t off = SMEM_SWIZZLE_128B(
                    (uint32_t)((wm * 64 + mi * 16 + a_row) * 128 + ks * 32 + a_kb));
                LDSM_X4(ah[mi][0], ah[mi][1], ah[mi][2], ah[mi][3], Ab + off);
                if (full)
                    LDSM_X4(al[mi][0], al[mi][1], al[mi][2], al[mi][3], Ab + GSM_TILE + off);
            }
            #pragma unroll
            for (int nb = 0; nb < 2; nb++) {
                const uint32_t off = SMEM_SWIZZLE_128B(
                    (uint32_t)((wn * 32 + nb * 16 + b_row) * 128 + ks * 32 + b_kb));
                uint32_t q0, q1, q2, q3;
                LDSM_X4(q0, q1, q2, q3, Bb + off);
                bh[nb * 2][0] = q0; bh[nb * 2][1] = q1;
                bh[nb * 2 + 1][0] = q2; bh[nb * 2 + 1][1] = q3;
            }
            #pragma unroll
            for (int mi = 0; mi < 4; mi++)
                #pragma unroll
                for (int ni = 0; ni < 4; ni++) {
                    MMA_F16(acc[mi][ni], ah[mi], bh[ni]);
                    if (full)
                        MMA_F16(acc[mi][ni], al[mi], bh[ni]);
                }
        }
        __syncthreads();
    }

    const int g = lane >> 2, t2 = (lane & 3) * 2;
    #pragma unroll
    for (int mi = 0; mi < 4; mi++) {
        const int row0 = bm + wm * 64 + mi * 16 + g;
        #pragma unroll
        for (int ni = 0; ni < 4; ni++) {
            const int col = bn + wn * 32 + ni * 8 + t2;
            float2 v0; v0.x = acc[mi][ni][0]; v0.y = acc[mi][ni][1];
            float2 v1; v1.x = acc[mi][ni][2]; v1.y = acc[mi][ni][3];
            *(float2*)&C[(size_t)row0 * N + col]       = v0;
            *(float2*)&C[(size_t)(row0 + 8) * N + col] = v1;
        }
    }
}

// ---------------------------------------------------------------------------
// postproc: warp-per-head RMSNorm + RoPE, packed 4B stores.
// Lane L owns d = {2L, 2L+1, 2L+64, 2L+65}; RoPE pairs (d, d+64) lane-local;
// adjacent-d outputs packed into one 32-bit store (full 128B warp lines).
// Gate sigmoid moved into the attention epilogue.
// ---------------------------------------------------------------------------
__global__ __launch_bounds__(256) void postproc(
    float* __restrict__ proj,
    const float* __restrict__ ropec, const float* __restrict__ ropes,
    __nv_bfloat16* __restrict__ qhi, __nv_bfloat16* __restrict__ qlo,
    __nv_bfloat16* __restrict__ khi, __nv_bfloat16* __restrict__ klo)
{
    const int row = blockIdx.x;
    const int bb  = row >> 11;
    const int l   = row & (LSEQ - 1);
    const int wid = threadIdx.x >> 5;
    const int lane = threadIdx.x & 31;
    const size_t base0 = (size_t)row * PW;

    const float c0 = ropec[l * 64 + 2 * lane],     s0 = ropes[l * 64 + 2 * lane];
    const float c1 = ropec[l * 64 + 2 * lane + 1], s1 = ropes[l * 64 + 2 * lane + 1];

    #pragma unroll
    for (int it = 0; it < 4; it++) {
        const int hh = wid + it * 8;
        const size_t base = base0 + hh * 128;
        float2 xa = *(const float2*)&proj[base + 2 * lane];       // d = 2L, 2L+1
        float2 xb = *(const float2*)&proj[base + 64 + 2 * lane];  // d = 2L+64, 2L+65
        float x0 = xa.x, x1 = xa.y, x2 = xb.x, x3 = xb.y;
        float v = x0 * x0 + x1 * x1 + x2 * x2 + x3 * x3;
        #pragma unroll
        for (int o = 16; o; o >>= 1) v += __shfl_xor_sync(0xffffffffu, v, o);
        float scl = 1.0f / sqrtf(v * 0.0078125f + 1e-5f);
        x0 *= scl; x1 *= scl; x2 *= scl; x3 *= scl;
        // RoPE pairs: (2L, 2L+64) and (2L+1, 2L+65)
        float y0 = x0 * c0 - x2 * s0;
        float y2 = x0 * s0 + x2 * c0;
        float y1 = x1 * c1 - x3 * s1;
        float y3 = x1 * s1 + x3 * c1;
        const float sc = (hh < 16) ? 0.08838834764831845f : 1.0f;
        y0 *= sc; y1 *= sc; y2 *= sc; y3 *= sc;
        __nv_bfloat16* dh = (hh < 16) ? qhi : khi;
        __nv_bfloat16* dl = (hh < 16) ? qlo : klo;
        const size_t ob = ((size_t)(bb * 16 + (hh & 15)) * LSEQ + l) * 128;
        uint32_t wA, wB;                         // packed hi (d,d+1) and (d+64,d+65)
        PACK_BF16X2(wA, y0, y1);
        PACK_BF16X2(wB, y2, y3);
        float hA0 = __uint_as_float(wA << 16);
        float hA1 = __uint_as_float(wA & 0xFFFF0000u);
        float hB0 = __uint_as_float(wB << 16);
        float hB1 = __uint_as_float(wB & 0xFFFF0000u);
        uint32_t lA, lB;
        PACK_BF16X2(lA, y0 - hA0, y1 - hA1);
        PACK_BF16X2(lB, y2 - hB0, y3 - hB1);
        *(uint32_t*)&dh[ob + 2 * lane]      = wA;
        *(uint32_t*)&dh[ob + 64 + 2 * lane] = wB;
        *(uint32_t*)&dl[ob + 2 * lane]      = lA;
        *(uint32_t*)&dl[ob + 64 + 2 * lane] = lB;
    }
}

// ---------------------------------------------------------------------------
// vsplit: V slice of proj [b,l,h,d] fp32 -> transposed bf16 hi/lo [b,h,d,l].
// 64-wide L tiles; packed 4B transposed stores (full 128B warp lines).
// ---------------------------------------------------------------------------
__global__ __launch_bounds__(256) void vsplit(const float* __restrict__ proj,
                                              __nv_bfloat16* __restrict__ vhit,
                                              __nv_bfloat16* __restrict__ vlot)
{
    __shared__ float t[64][33];
    const int l0 = blockIdx.x * 64;
    const int d0 = blockIdx.y * 32;
    const int bh = blockIdx.z;
    const int b = bh >> 4, h = bh & 15;
    const int x = threadIdx.x & 31, y = threadIdx.x >> 5;   // x: d/lane, y: 0..7
    // load 64 l-rows x 32 d-cols
    #pragma unroll
    for (int i = 0; i < 8; i++) {
        int ll = y + i * 8;
        t[ll][x] = proj[((size_t)b * LSEQ + l0 + ll) * PW + 4096 + h * 128 + d0 + x];
    }
    __syncthreads();
    // transposed store: thread handles d = y + i*8, l pair (2x, 2x+1)
    #pragma unroll
    for (int i = 0; i < 4; i++) {
        int d = y + i * 8;
        float v0 = t[2 * x][d];
        float v1 = t[2 * x + 1][d];
        uint32_t wH;
        PACK_BF16X2(wH, v0, v1);
        float h0 = __uint_as_float(wH << 16);
        float h1 = __uint_as_float(wH & 0xFFFF0000u);
        uint32_t wL;
        PACK_BF16X2(wL, v0 - h0, v1 - h1);
        size_t o = ((size_t)bh * 128 + d0 + d) * LSEQ + l0 + 2 * x;
        *(uint32_t*)&vhit[o] = wH;
        *(uint32_t*)&vlot[o] = wL;
        d = y + i * 8 + 32;   // second d half handled by same thread
        v0 = t[2 * x][d - 32 + 0];    // placeholder avoided below
    }
    // handle remaining d rows 32..? (d0 tiles are 32 wide; loop above covers 4*8=32) — done.
}

// ---------------------------------------------------------------------------
// HMMA bf16x3 causal flash attention (BM=64, 4 warps, 98 KB -> 2 CTAs/SM).
// K/V split cp.async groups. Gate sigmoid applied in epilogue (raw gate read).
// ---------------------------------------------------------------------------
#define ASM_QH 0
#define ASM_QL 16384
#define ASM_KH 32768
#define ASM_KL 49152
#define ASM_VH 65536
#define ASM_VL 81920
#define ATTN_SMEM 98304

__global__ __launch_bounds__(128) void attn_hmma(
    const __nv_bfloat16* __restrict__ qhi, const __nv_bfloat16* __restrict__ qlo,
    const __nv_bfloat16* __restrict__ khi, const __nv_bfloat16* __restrict__ klo,
    const __nv_bfloat16* __restrict__ vhit, const __nv_bfloat16* __restrict__ vlot,
    const float* __restrict__ proj,
    __half* __restrict__ att_hi, __half* __restrict__ att_lo)
{
    extern __shared__ char smc[];
    const uint32_t sb = smem_to_u32(smc);
    const int tid = threadIdx.x, wid = tid >> 5, lane = tid & 31;
    const int qb = (int)gridDim.x - 1 - (int)blockIdx.x;
    const int bh = blockIdx.y;
    const int b = bh >> 4, h = bh & 15;
    const int q0 = qb << 6;
    const size_t hbase = (size_t)bh * LSEQ * 128;
    const size_t vbase = (size_t)bh * 128 * LSEQ;
    const size_t tokbase = (size_t)b * LSEQ;

    const int r0 = tid >> 3;
    const int c16 = tid & 7;

    const int lr = lane & 7;
    const int a_row = lr + ((lane >> 3) & 1) * 8;
    const int a_kb  = ((lane >> 4) & 1) * 16;
    const int b_row = lr + ((lane >> 4) & 1) * 8;
    const int b_kb  = ((lane >> 3) & 1) * 16;
    const int g  = lane >> 2;
    const int t2 = (lane & 3) * 2;

    #pragma unroll
    for (int i = 0; i < 4; i++) {
        const int r = r0 + i * 16;
        const uint32_t so = SMEM_SWIZZLE_128B((uint32_t)(r * 128 + c16 * 16));
        const size_t gq = hbase + (size_t)(q0 + r) * 128 + c16 * 8;
        CP_ASYNC_16(sb + ASM_QH        + so, qhi + gq);
        CP_ASYNC_16(sb + ASM_QH + 8192 + so, qhi + gq + 64);
        CP_ASYNC_16(sb + ASM_QL        + so, qlo + gq);
        CP_ASYNC_16(sb + ASM_QL + 8192 + so, qlo + gq + 64);
    }
    CP_ASYNC_COMMIT();

    float o[16][4];
    #pragma unroll
    for (int nt = 0; nt < 16; nt++)
        #pragma unroll
        for (int j = 0; j < 4; j++) o[nt][j] = 0.f;
    float m0 = -1e30f, m1 = -1e30f, lsum0 = 0.f, lsum1 = 0.f;

    for (int kt = 0; kt <= qb; kt++) {
        const int k0 = kt << 6;
        // K tiles (own group)
        #pragma unroll
        for (int i = 0; i < 4; i++) {
            const int r = r0 + i * 16;
            const uint32_t so = SMEM_SWIZZLE_128B((uint32_t)(r * 128 + c16 * 16));
            const size_t gk = hbase + (size_t)(k0 + r) * 128 + c16 * 8;
            CP_ASYNC_16(sb + ASM_KH        + so, khi + gk);
            CP_ASYNC_16(sb + ASM_KH + 8192 + so, khi + gk + 64);
            CP_ASYNC_16(sb + ASM_KL        + so, klo + gk);
            CP_ASYNC_16(sb + ASM_KL + 8192 + so, klo + gk + 64);
        }
        CP_ASYNC_COMMIT();
        // V tiles (separate group; lands during S + softmax)
        #pragma unroll
        for (int i = 0; i < 8; i++) {
            const int d = r0 + i * 16;
            const uint32_t so = SMEM_SWIZZLE_128B((uint32_t)(d * 128 + c16 * 16));
            const size_t gv = vbase + (size_t)d * LSEQ + k0 + c16 * 8;
            CP_ASYNC_16(sb + ASM_VH + so, vhit + gv);
            CP_ASYNC_16(sb + ASM_VL + so, vlot + gv);
        }
        CP_ASYNC_COMMIT();
        CP_ASYNC_WAIT_1();
        __syncthreads();

        float s[8][4];
        #pragma unroll
        for (int nb = 0; nb < 8; nb++)
            #pragma unroll
            for (int j = 0; j < 4; j++) s[nb][j] = 0.f;

        #pragma unroll
        for (int ks = 0; ks < 8; ks++) {
            const uint32_t qt = sb + ASM_QH + (ks >> 2) * 8192;
            const uint32_t kt_ = sb + ASM_KH + (ks >> 2) * 8192;
            const uint32_t kb = (ks & 3) * 32;
            uint32_t ah[4], al[4];
            const uint32_t aoff = SMEM_SWIZZLE_128B(
                (uint32_t)((wid * 16 + a_row) * 128 + kb + a_kb));
            LDSM_X4(ah[0], ah[1], ah[2], ah[3], qt + aoff);
            LDSM_X4(al[0], al[1], al[2], al[3], qt + 16384 + aoff);
            #pragma unroll
            for (int ng = 0; ng < 4; ng++) {
                const uint32_t boff = SMEM_SWIZZLE_128B(
                    (uint32_t)((ng * 16 + b_row) * 128 + kb + b_kb));
                uint32_t h0, h1, h2, h3, l0_, l1_, l2_, l3_;
                LDSM_X4(h0, h1, h2, h3, kt_ + boff);
                LDSM_X4(l0_, l1_, l2_, l3_, kt_ + 16384 + boff);
                uint32_t bh0[2] = {h0, h1}, bh1[2] = {h2, h3};
                uint32_t bl0[2] = {l0_, l1_}, bl1[2] = {l2_, l3_};
                MMA_16816(s[ng * 2],     ah, bh0);
                MMA_16816(s[ng * 2 + 1], ah, bh1);
                MMA_16816(s[ng * 2],     ah, bl0);
                MMA_16816(s[ng * 2 + 1], ah, bl1);
                MMA_16816(s[ng * 2],     al, bh0);
                MMA_16816(s[ng * 2 + 1], al, bh1);
            }
        }

        if (kt == qb) {
            const int qr = wid * 16 + g;
            #pragma unroll
            for (int nb = 0; nb < 8; nb++) {
                const int col = nb * 8 + t2;
                if (col     > qr)     s[nb][0] = -1e30f;
                if (col + 1 > qr)     s[nb][1] = -1e30f;
                if (col     > qr + 8) s[nb][2] = -1e30f;
                if (col + 1 > qr + 8) s[nb][3] = -1e30f;
            }
        }

        float mx0 = -1e30f, mx1 = -1e30f;
        #pragma unroll
        for (int nb = 0; nb < 8; nb++) {
            mx0 = fmaxf(mx0, fmaxf(s[nb][0], s[nb][1]));
            mx1 = fmaxf(mx1, fmaxf(s[nb][2], s[nb][3]));
        }
        mx0 = fmaxf(mx0, __shfl_xor_sync(0xffffffffu, mx0, 1));
        mx0 = fmaxf(mx0, __shfl_xor_sync(0xffffffffu, mx0, 2));
        mx1 = fmaxf(mx1, __shfl_xor_sync(0xffffffffu, mx1, 1));
        mx1 = fmaxf(mx1, __shfl_xor_sync(0xffffffffu, mx1, 2));
        const float mn0 = fmaxf(m0, mx0), mn1 = fmaxf(m1, mx1);
        const float al0 = __expf(m0 - mn0), al1 = __expf(m1 - mn1);
        m0 = mn0; m1 = mn1;

        float rs0 = 0.f, rs1 = 0.f;
        uint32_t pHg[8], pHg8[8], pLg[8], pLg8[8];
        #pragma unroll
        for (int nb = 0; nb < 8; nb++) {
            float p0 = __expf(s[nb][0] - mn0), p1 = __expf(s[nb][1] - mn0);
            float p2 = __expf(s[nb][2] - mn1), p3 = __expf(s[nb][3] - mn1);
            rs0 += p0 + p1; rs1 += p2 + p3;
            uint32_t hg, hg8;
            PACK_BF16X2(hg,  p0, p1);
            PACK_BF16X2(hg8, p2, p3);
            pHg[nb] = hg; pHg8[nb] = hg8;
            float h0 = __uint_as_float(hg << 16);
            float h1 = __uint_as_float(hg & 0xFFFF0000u);
            float h2 = __uint_as_float(hg8 << 16);
            float h3 = __uint_as_float(hg8 & 0xFFFF0000u);
            uint32_t lg, lg8;
            PACK_BF16X2(lg,  p0 - h0, p1 - h1);
            PACK_BF16X2(lg8, p2 - h2, p3 - h3);
            pLg[nb] = lg; pLg8[nb] = lg8;
        }
        rs0 += __shfl_xor_sync(0xffffffffu, rs0, 1);
        rs0 += __shfl_xor_sync(0xffffffffu, rs0, 2);
        rs1 += __shfl_xor_sync(0xffffffffu, rs1, 1);
        rs1 += __shfl_xor_sync(0xffffffffu, rs1, 2);
        lsum0 = lsum0 * al0 + rs0;
        lsum1 = lsum1 * al1 + rs1;
        #pragma unroll
        for (int nt = 0; nt < 16; nt++) {
            o[nt][0] *= al0; o[nt][1] *= al0;
            o[nt][2] *= al1; o[nt][3] *= al1;
        }

        CP_ASYNC_WAIT_0();
        __syncthreads();

        #pragma unroll
        for (int kn = 0; kn < 4; kn++) {
            uint32_t aH[4] = {pHg[2 * kn], pHg8[2 * kn], pHg[2 * kn + 1], pHg8[2 * kn + 1]};
            uint32_t aL[4] = {pLg[2 * kn], pLg8[2 * kn], pLg[2 * kn + 1], pLg8[2 * kn + 1]};
            #pragma unroll
            for (int ng = 0; ng < 8; ng++) {
                const uint32_t boff = SMEM_SWIZZLE_128B(
                    (uint32_t)((ng * 16 + b_row) * 128 + kn * 32 + b_kb));
                uint32_t h0, h1, h2, h3, l0_, l1_, l2_, l3_;
                LDSM_X4(h0, h1, h2, h3, sb + ASM_VH + boff);
                LDSM_X4(l0_, l1_, l2_, l3_, sb + ASM_VL + boff);
                uint32_t vh0[2] = {h0, h1}, vh1[2] = {h2, h3};
                uint32_t vl0[2] = {l0_, l1_}, vl1[2] = {l2_, l3_};
                MMA_16816(o[ng * 2],     aH, vh0);
                MMA_16816(o[ng * 2 + 1], aH, vh1);
                MMA_16816(o[ng * 2],     aH, vl0);
                MMA_16816(o[ng * 2 + 1], aH, vl1);
                MMA_16816(o[ng * 2],     aL, vh0);
                MMA_16816(o[ng * 2 + 1], aL, vh1);
            }
        }
        __syncthreads();
    }

    // epilogue: normalize, sigmoid(gate), split to fp16 hi/lo
    const float inv0 = 1.0f / lsum0;
    const float inv1 = 1.0f / lsum1;
    const int qr0 = q0 + wid * 16 + g;
    const int qr1 = qr0 + 8;
    const size_t prow0 = (tokbase + qr0) * PW + 6144 + h * 128;
    const size_t prow1 = (tokbase + qr1) * PW + 6144 + h * 128;
    const size_t arow0 = (tokbase + qr0) * HIDN + h * 128;
    const size_t arow1 = (tokbase + qr1) * HIDN + h * 128;
    #pragma unroll
    for (int nb = 0; nb < 16; nb++) {
        const int d = nb * 8 + t2;
        float2 g0 = *(const float2*)&proj[prow0 + d];
        float2 g1 = *(const float2*)&proj[prow1 + d];
        g0.x = 1.0f / (1.0f + __expf(-g0.x));
        g0.y = 1.0f / (1.0f + __expf(-g0.y));
        g1.x = 1.0f / (1.0f + __expf(-g1.x));
        g1.y = 1.0f / (1.0f + __expf(-g1.y));
        float x0 = o[nb][0] * inv0 * g0.x;
        float x1 = o[nb][1] * inv0 * g0.y;
        float x2 = o[nb][2] * inv1 * g1.x;
        float x3 = o[nb][3] * inv1 * g1.y;
        __half hh0 = __float2half_rn(x0), hh1 = __float2half_rn(x1);
        __half hh2 = __float2half_rn(x2), hh3 = __float2half_rn(x3);
        __half ll0 = __float2half_rn(x0 - __half2float(hh0));
        __half ll1 = __float2half_rn(x1 - __half2float(hh1));
        __half ll2 = __float2half_rn(x2 - __half2float(hh2));
        __half ll3 = __float2half_rn(x3 - __half2float(hh3));
        uint32_t hp0 = ((uint32_t)__half_as_ushort(hh1) << 16) | __half_as_ushort(hh0);
        uint32_t hp1 = ((uint32_t)__half_as_ushort(hh3) << 16) | __half_as_ushort(hh2);
        uint32_t lp0 = ((uint32_t)__half_as_ushort(ll1) << 16) | __half_as_ushort(ll0);
        uint32_t lp1 = ((uint32_t)__half_as_ushort(ll3) << 16) | __half_as_ushort(ll2);
        *(uint32_t*)&att_hi[arow0 + d] = hp0;
        *(uint32_t*)&att_lo[arow0 + d] = lp0;
        *(uint32_t*)&att_hi[arow1 + d] = hp1;
        *(uint32_t*)&att_lo[arow1 + d] = lp1;
    }
}

// ---------------------------------------------------------------------------
extern "C" void kernel_launch(void* const* d_in, const int* in_sizes, int n_in,
                              void* d_out, int out_size)
{
    const float* hs    = (const float*)d_in[0];   // (4,2048,2048)
    const float* wqkvg = (const float*)d_in[1];   // (2048,8192)
    const float* wout  = (const float*)d_in[2];   // (2048,2048)
    float* out = (float*)d_out;

    float* proj; float *ropec, *ropes;
    __half *hs_hi, *hs_lo, *wq_hi, *wo_hi, *at_hi, *at_lo;
    __nv_bfloat16 *q_hi, *q_lo, *k_hi, *k_lo, *v_hi, *v_lo;
    cudaGetSymbolAddress((void**)&proj,  g_proj);
    cudaGetSymbolAddress((void**)&ropec, g_ropec);
    cudaGetSymbolAddress((void**)&ropes, g_ropes);
    cudaGetSymbolAddress((void**)&hs_hi, g_hs_hi);
    cudaGetSymbolAddress((void**)&hs_lo, g_hs_lo);
    cudaGetSymbolAddress((void**)&wq_hi, g_wq_hi);
    cudaGetSymbolAddress((void**)&wo_hi, g_wo_hi);
    cudaGetSymbolAddress((void**)&at_hi, g_at_hi);
    cudaGetSymbolAddress((void**)&at_lo, g_at_lo);
    cudaGetSymbolAddress((void**)&q_hi,  g_q_hi);
    cudaGetSymbolAddress((void**)&q_lo,  g_q_lo);
    cudaGetSymbolAddress((void**)&k_hi,  g_k_hi);
    cudaGetSymbolAddress((void**)&k_lo,  g_k_lo);
    cudaGetSymbolAddress((void**)&v_hi,  g_v_hi);
    cudaGetSymbolAddress((void**)&v_lo,  g_v_lo);

    cudaFuncSetAttribute(gemm_f16x2, cudaFuncAttributeMaxDynamicSharedMemorySize, GSM_TOTAL);
    cudaFuncSetAttribute(attn_hmma,  cudaFuncAttributeMaxDynamicSharedMemorySize, ATTN_SMEM);

    // 0) RoPE table + fp16 splits + weight transposes
    rope_kernel<<<LSEQ, 64>>>(ropec, ropes);
    split_kernel<<<(TOK * HIDN / 4 + 255) / 256, 256>>>(hs, hs_hi, hs_lo, TOK * HIDN / 4);
    tsplit_kernel<<<dim3(PW / 32,   HIDN / 32), 256>>>(wqkvg, wq_hi, HIDN, PW);
    tsplit_kernel<<<dim3(HIDN / 32, HIDN / 32), 256>>>(wout,  wo_hi, HIDN, HIDN);

    // 1) QKVG projection (fp16 2-pass; gate columns [6144,8192) use 1 pass)
    gemm_f16x2<<<dim3(PW / 128, TOK / 128), 256, GSM_TOTAL>>>(
        hs_hi, hs_lo, wq_hi, proj, TOK, PW, HIDN, 6144);

    // 2) RMSNorm + RoPE -> bf16 splits (packed stores); gate handled in attn
    postproc<<<TOK, 256>>>(proj, ropec, ropes, q_hi, q_lo, k_hi, k_lo);

    // 2b) V transpose + split (64-wide L tiles, packed stores)
    vsplit<<<dim3(LSEQ / 64, 4, 64), 256>>>(proj, v_hi, v_lo);

    // 3) HMMA bf16x3 causal flash attention (sigmoid fused in epilogue)
    attn_hmma<<<dim3(32, 64), 128, ATTN_SMEM>>>(
        q_hi, q_lo, k_hi, k_lo, v_hi, v_lo, proj, at_hi, at_lo);

    // 4) output projection (fp16 2-pass everywhere)
    gemm_f16x2<<<dim3(HIDN / 128, TOK / 128), 256, GSM_TOTAL>>>(
        at_hi, at_lo, wo_hi, out, TOK, HIDN, HIDN, HIDN);
}

// round 16
// speedup vs baseline: 1.0576x; 1.0576x over previous
#include <cuda_runtime.h>
#include <cuda_bf16.h>
#include <cuda_fp16.h>
#include <cstdint>
#include <math.h>

// Problem constants
#define TOK   8192      // B*L
#define HIDN  2048
#define PW    8192      // QKV (6144) + gate (2048)
#define LSEQ  2048

// ---------------------------------------------------------------------------
// Global scratch (allocation-free rule: device globals)
// ---------------------------------------------------------------------------
__device__ float   g_proj [(size_t)TOK * PW];    // 256 MB fp32
__device__ __half  g_hs_hi[(size_t)TOK * HIDN];  // activations fp16 2-split
__device__ __half  g_hs_lo[(size_t)TOK * HIDN];
__device__ __half  g_wq_hi[(size_t)PW  * HIDN];  // W_qkvg^T [N][K] fp16 single
__device__ __half  g_wo_hi[(size_t)HIDN* HIDN];  // W_out^T  [N][K] fp16 single
__device__ __half  g_at_hi[(size_t)TOK * HIDN];  // attention out fp16 2-split
__device__ __half  g_at_lo[(size_t)TOK * HIDN];
// head-major attention operands (fp16 path): q 2-split, k/v single
__device__ __half  g_q_hi[(size_t)64 * LSEQ * 128];
__device__ __half  g_q_lo[(size_t)64 * LSEQ * 128];
__device__ __half  g_k_hi[(size_t)64 * LSEQ * 128];
__device__ __half  g_v_hi[(size_t)64 * 128 * LSEQ];
// RoPE table
__device__ float g_ropec[LSEQ * 64];
__device__ float g_ropes[LSEQ * 64];

// ---------------------------------------------------------------------------
// Helpers
// ---------------------------------------------------------------------------
__device__ __forceinline__ uint32_t smem_to_u32(const void* smem_ptr) {
    uint32_t addr;
    asm("{ .reg .u64 tmp; cvta.to.shared.u64 tmp, %1; cvt.u32.u64 %0, tmp; }"
        : "=r"(addr) : "l"(smem_ptr));
    return addr;
}

#define SMEM_SWIZZLE_128B(byte_offset) \
    ((byte_offset) ^ ((((uint32_t)(byte_offset)) >> 3) & 0x70u))

#define CP_ASYNC_16(smem_u32, gptr) \
    asm volatile("cp.async.cg.shared.global [%0], [%1], 16;" \
                 :: "r"(smem_u32), "l"(gptr) : "memory")
#define CP_ASYNC_COMMIT() asm volatile("cp.async.commit_group;" ::: "memory")
#define CP_ASYNC_WAIT_1() asm volatile("cp.async.wait_group 1;" ::: "memory")
#define CP_ASYNC_WAIT_0() asm volatile("cp.async.wait_group 0;" ::: "memory")

#define LDSM_X4(r0, r1, r2, r3, addr) \
    asm volatile("ldmatrix.sync.aligned.m8n8.x4.shared.b16 {%0,%1,%2,%3}, [%4];" \
                 : "=r"(r0), "=r"(r1), "=r"(r2), "=r"(r3) : "r"(addr))

// fp16 MMA (GEMMs + attention)
#define MMA_F16(c, a, b) \
    asm volatile("mma.sync.aligned.m16n8k16.row.col.f32.f16.f16.f32 " \
                 "{%0,%1,%2,%3}, {%4,%5,%6,%7}, {%8,%9}, {%0,%1,%2,%3};" \
                 : "+f"((c)[0]), "+f"((c)[1]), "+f"((c)[2]), "+f"((c)[3]) \
                 : "r"((a)[0]), "r"((a)[1]), "r"((a)[2]), "r"((a)[3]), \
                   "r"((b)[0]), "r"((b)[1]))

__device__ __forceinline__ uint32_t pack_h2(__half lo, __half hi) {
    return ((uint32_t)__half_as_ushort(hi) << 16) | __half_as_ushort(lo);
}

// ---------------------------------------------------------------------------
// RoPE table (fp64 once)
// ---------------------------------------------------------------------------
__global__ void rope_kernel(float* __restrict__ cs, float* __restrict__ sn)
{
    const int i = threadIdx.x;     // 0..63
    const int l = blockIdx.x;      // 0..2047
    double f   = pow(10000.0, -(double)i / 64.0);
    double ang = (double)l * f;
    double s, c;
    sincos(ang, &s, &c);
    cs[l * 64 + i] = (float)c;
    sn[l * 64 + i] = (float)s;
}

// ---------------------------------------------------------------------------
// elementwise fp32 -> fp16 hi/lo split (activations)
// ---------------------------------------------------------------------------
__global__ __launch_bounds__(256) void split_kernel(const float* __restrict__ x,
                                                    __half* __restrict__ hi,
                                                    __half* __restrict__ lo, int n4)
{
    int i = blockIdx.x * 256 + threadIdx.x;
    if (i >= n4) return;
    float4 v = ((const float4*)x)[i];
    float vv[4];
    vv[0] = v.x; vv[1] = v.y; vv[2] = v.z; vv[3] = v.w;
    __half hbuf[4], lbuf[4];
    #pragma unroll
    for (int j = 0; j < 4; j++) {
        __half h = __float2half_rn(vv[j]);
        hbuf[j] = h;
        lbuf[j] = __float2half_rn(vv[j] - __half2float(h));
    }
    *(uint2*)&hi[(size_t)i * 4] = *(const uint2*)hbuf;
    *(uint2*)&lo[(size_t)i * 4] = *(const uint2*)lbuf;
}

// ---------------------------------------------------------------------------
// W [K][N] fp32 -> Wt_hi [N][K] fp16 (transpose)
// ---------------------------------------------------------------------------
__global__ __launch_bounds__(256) void tsplit_kernel(const float* __restrict__ W,
                                                     __half* __restrict__ hi,
                                                     int K, int N)
{
    __shared__ float t[32][33];
    const int bn = blockIdx.x * 32;
    const int bk = blockIdx.y * 32;
    const int x = threadIdx.x & 31;
    const int y4 = (threadIdx.x >> 5) * 4;
    #pragma unroll
    for (int r = 0; r < 4; r++)
        t[y4 + r][x] = W[(size_t)(bk + y4 + r) * N + bn + x];
    __syncthreads();
    #pragma unroll
    for (int r = 0; r < 4; r++)
        hi[(size_t)(bn + y4 + r) * K + bk + x] = __float2half_rn(t[x][y4 + r]);
}

// ---------------------------------------------------------------------------
// fp16 2-pass GEMM (round-13 config, proven at 2070us):
// 128x128 CTA tile, 256 threads, BK=64, 2-stage cp.async, 96 KB smem.
// CTAs with bn >= n_full use a single (Ah only) pass — gate-column fast path.
// ---------------------------------------------------------------------------
#define GSM_TILE   16384
#define GSM_STAGE  (3 * GSM_TILE)
#define GSM_TOTAL  (2 * GSM_STAGE)

__global__ __launch_bounds__(256, 2) void gemm_f16x2(
    const __half* __restrict__ Ahi, const __half* __restrict__ Alo,
    const __half* __restrict__ Bh,
    float* __restrict__ C, int M, int N, int K, int n_full)
{
    extern __shared__ char smc[];
    const uint32_t sb = smem_to_u32(smc);
    const int tid  = threadIdx.x;
    const int wid  = tid >> 5;
    const int lane = tid & 31;
    const int wm   = wid & 1;
    const int wn   = wid >> 1;
    const int bm   = blockIdx.y << 7;
    const int bn   = blockIdx.x << 7;
    const bool full = (bn < n_full);

    const int r0  = tid >> 3;
    const int c16 = tid & 7;

    const __half* srcs[3];
    srcs[0] = Ahi + (size_t)bm * K;
    srcs[1] = Alo + (size_t)bm * K;
    srcs[2] = Bh  + (size_t)bn * K;

    const int nc = K >> 6;

    auto issue_chunk = [&](int c, int buf) {
        const int k0 = c << 6;
        const uint32_t bufb = sb + buf * GSM_STAGE;
        #pragma unroll
        for (int t = 0; t < 3; t++) {
            if (t == 1 && !full) continue;
            const __half* s = srcs[t] + k0;
            #pragma unroll
            for (int rr = 0; rr < 4; rr++) {
                const int r = r0 + rr * 32;
                const uint32_t so = bufb + t * GSM_TILE +
                    SMEM_SWIZZLE_128B((uint32_t)(r * 128 + c16 * 16));
                CP_ASYNC_16(so, s + (size_t)r * K + c16 * 8);
            }
        }
    };

    float acc[4][4][4];
    #pragma unroll
    for (int mi = 0; mi < 4; mi++)
        #pragma unroll
        for (int ni = 0; ni < 4; ni++)
            #pragma unroll
            for (int j = 0; j < 4; j++) acc[mi][ni][j] = 0.f;

    const int lr   = lane & 7;
    const int a_row = lr + ((lane >> 3) & 1) * 8;
    const int a_kb  = ((lane >> 4) & 1) * 16;
    const int b_row = lr + ((lane >> 4) & 1) * 8;
    const int b_kb  = ((lane >> 3) & 1) * 16;

    issue_chunk(0, 0);
    CP_ASYNC_COMMIT();

    for (int c = 0; c < nc; c++) {
        const int buf = c & 1;
        if (c + 1 < nc) {
            issue_chunk(c + 1, buf ^ 1);
            CP_ASYNC_COMMIT();
            CP_ASYNC_WAIT_1();
        } else {
            CP_ASYNC_WAIT_0();
        }
        __syncthreads();

        const uint32_t Ab = sb + buf * GSM_STAGE;
        const uint32_t Bb = Ab + 2 * GSM_TILE;

        #pragma unroll
        for (int ks = 0; ks < 4; ks++) {
            uint32_t ah[4][4], al[4][4], bh[4][2];
            #pragma unroll
            for (int mi = 0; mi < 4; mi++) {
                const uint32_t off = SMEM_SWIZZLE_128B(
                    (uint32_t)((wm * 64 + mi * 16 + a_row) * 128 + ks * 32 + a_kb));
                LDSM_X4(ah[mi][0], ah[mi][1], ah[mi][2], ah[mi][3], Ab + off);
                if (full)
                    LDSM_X4(al[mi][0], al[mi][1], al[mi][2], al[mi][3], Ab + GSM_TILE + off);
            }
            #pragma unroll
            for (int nb = 0; nb < 2; nb++) {
                const uint32_t off = SMEM_SWIZZLE_128B(
                    (uint32_t)((wn * 32 + nb * 16 + b_row) * 128 + ks * 32 + b_kb));
                uint32_t q0, q1, q2, q3;
                LDSM_X4(q0, q1, q2, q3, Bb + off);
                bh[nb * 2][0] = q0; bh[nb * 2][1] = q1;
                bh[nb * 2 + 1][0] = q2; bh[nb * 2 + 1][1] = q3;
            }
            #pragma unroll
            for (int mi = 0; mi < 4; mi++)
                #pragma unroll
                for (int ni = 0; ni < 4; ni++) {
                    MMA_F16(acc[mi][ni], ah[mi], bh[ni]);
                    if (full)
                        MMA_F16(acc[mi][ni], al[mi], bh[ni]);
                }
        }
        __syncthreads();
    }

    const int g = lane >> 2, t2 = (lane & 3) * 2;
    #pragma unroll
    for (int mi = 0; mi < 4; mi++) {
        const int row0 = bm + wm * 64 + mi * 16 + g;
        #pragma unroll
        for (int ni = 0; ni < 4; ni++) {
            const int col = bn + wn * 32 + ni * 8 + t2;
            float2 v0; v0.x = acc[mi][ni][0]; v0.y = acc[mi][ni][1];
            float2 v1; v1.x = acc[mi][ni][2]; v1.y = acc[mi][ni][3];
            *(float2*)&C[(size_t)row0 * N + col]       = v0;
            *(float2*)&C[(size_t)(row0 + 8) * N + col] = v1;
        }
    }
}

// ---------------------------------------------------------------------------
// postproc: warp-per-head RMSNorm + RoPE, packed 4B fp16 stores.
// Lane L owns d = {2L, 2L+1, 2L+64, 2L+65}.
// q: fp16 hi/lo 2-split (prescaled). k: single fp16. Gate handled in attn.
// ---------------------------------------------------------------------------
__global__ __launch_bounds__(256) void postproc(
    float* __restrict__ proj,
    const float* __restrict__ ropec, const float* __restrict__ ropes,
    __half* __restrict__ qhi, __half* __restrict__ qlo,
    __half* __restrict__ khi)
{
    const int row = blockIdx.x;
    const int bb  = row >> 11;
    const int l   = row & (LSEQ - 1);
    const int wid = threadIdx.x >> 5;
    const int lane = threadIdx.x & 31;
    const size_t base0 = (size_t)row * PW;

    const float c0 = ropec[l * 64 + 2 * lane],     s0 = ropes[l * 64 + 2 * lane];
    const float c1 = ropec[l * 64 + 2 * lane + 1], s1 = ropes[l * 64 + 2 * lane + 1];

    #pragma unroll
    for (int it = 0; it < 4; it++) {
        const int hh = wid + it * 8;
        const size_t base = base0 + hh * 128;
        float2 xa = *(const float2*)&proj[base + 2 * lane];       // d = 2L, 2L+1
        float2 xb = *(const float2*)&proj[base + 64 + 2 * lane];  // d = 2L+64, 2L+65
        float x0 = xa.x, x1 = xa.y, x2 = xb.x, x3 = xb.y;
        float v = x0 * x0 + x1 * x1 + x2 * x2 + x3 * x3;
        #pragma unroll
        for (int o = 16; o; o >>= 1) v += __shfl_xor_sync(0xffffffffu, v, o);
        float scl = 1.0f / sqrtf(v * 0.0078125f + 1e-5f);
        x0 *= scl; x1 *= scl; x2 *= scl; x3 *= scl;
        float y0 = x0 * c0 - x2 * s0;
        float y2 = x0 * s0 + x2 * c0;
        float y1 = x1 * c1 - x3 * s1;
        float y3 = x1 * s1 + x3 * c1;
        const size_t ob = ((size_t)(bb * 16 + (hh & 15)) * LSEQ + l) * 128;
        if (hh < 16) {
            const float sc = 0.08838834764831845f;
            y0 *= sc; y1 *= sc; y2 *= sc; y3 *= sc;
            __half hA0 = __float2half_rn(y0), hA1 = __float2half_rn(y1);
            __half hB0 = __float2half_rn(y2), hB1 = __float2half_rn(y3);
            *(uint32_t*)&qhi[ob + 2 * lane]      = pack_h2(hA0, hA1);
            *(uint32_t*)&qhi[ob + 64 + 2 * lane] = pack_h2(hB0, hB1);
            *(uint32_t*)&qlo[ob + 2 * lane]      = pack_h2(
                __float2half_rn(y0 - __half2float(hA0)),
                __float2half_rn(y1 - __half2float(hA1)));
            *(uint32_t*)&qlo[ob + 64 + 2 * lane] = pack_h2(
                __float2half_rn(y2 - __half2float(hB0)),
                __float2half_rn(y3 - __half2float(hB1)));
        } else {
            *(uint32_t*)&khi[ob + 2 * lane] =
                pack_h2(__float2half_rn(y0), __float2half_rn(y1));
            *(uint32_t*)&khi[ob + 64 + 2 * lane] =
                pack_h2(__float2half_rn(y2), __float2half_rn(y3));
        }
    }
}

// ---------------------------------------------------------------------------
// vsplit: V slice of proj [b,l,h,d] fp32 -> transposed single fp16 [b,h,d,l]
// ---------------------------------------------------------------------------
__global__ __launch_bounds__(256) void vsplit(const float* __restrict__ proj,
                                              __half* __restrict__ vhit)
{
    __shared__ float t[64][33];
    const int l0 = blockIdx.x * 64;
    const int d0 = blockIdx.y * 32;
    const int bh = blockIdx.z;
    const int b = bh >> 4, h = bh & 15;
    const int x = threadIdx.x & 31, y = threadIdx.x >> 5;
    #pragma unroll
    for (int i = 0; i < 8; i++) {
        int ll = y + i * 8;
        t[ll][x] = proj[((size_t)b * LSEQ + l0 + ll) * PW + 4096 + h * 128 + d0 + x];
    }
    __syncthreads();
    #pragma unroll
    for (int i = 0; i < 4; i++) {
        int d = y + i * 8;
        float v0 = t[2 * x][d];
        float v1 = t[2 * x + 1][d];
        size_t o = ((size_t)bh * 128 + d0 + d) * LSEQ + l0 + 2 * x;
        *(uint32_t*)&vhit[o] = pack_h2(__float2half_rn(v0), __float2half_rn(v1));
    }
}

// ---------------------------------------------------------------------------
// fp16 2-pass causal flash attention. BM=64, 4 warps, 64 KB smem (3 CTAs/SM).
// S = (Qh+Ql) K^T (2 MMAs), O = (Ph+Pl) V (2 MMAs). Gate sigmoid in epilogue.
// ---------------------------------------------------------------------------
#define ASM_QH 0
#define ASM_QL 16384
#define ASM_KH 32768
#define ASM_VH 49152
#define ATTN_SMEM 65536

__global__ __launch_bounds__(128) void attn_hmma(
    const __half* __restrict__ qhi, const __half* __restrict__ qlo,
    const __half* __restrict__ khi, const __half* __restrict__ vhit,
    const float* __restrict__ proj,
    __half* __restrict__ att_hi, __half* __restrict__ att_lo)
{
    extern __shared__ char smc[];
    const uint32_t sb = smem_to_u32(smc);
    const int tid = threadIdx.x, wid = tid >> 5, lane = tid & 31;
    const int qb = (int)gridDim.x - 1 - (int)blockIdx.x;
    const int bh = blockIdx.y;
    const int b = bh >> 4, h = bh & 15;
    const int q0 = qb << 6;
    const size_t hbase = (size_t)bh * LSEQ * 128;
    const size_t vbase = (size_t)bh * 128 * LSEQ;
    const size_t tokbase = (size_t)b * LSEQ;

    const int r0 = tid >> 3;
    const int c16 = tid & 7;

    const int lr = lane & 7;
    const int a_row = lr + ((lane >> 3) & 1) * 8;
    const int a_kb  = ((lane >> 4) & 1) * 16;
    const int b_row = lr + ((lane >> 4) & 1) * 8;
    const int b_kb  = ((lane >> 3) & 1) * 16;
    const int g  = lane >> 2;
    const int t2 = (lane & 3) * 2;

    // Q tiles (persistent, 2-split)
    #pragma unroll
    for (int i = 0; i < 4; i++) {
        const int r = r0 + i * 16;
        const uint32_t so = SMEM_SWIZZLE_128B((uint32_t)(r * 128 + c16 * 16));
        const size_t gq = hbase + (size_t)(q0 + r) * 128 + c16 * 8;
        CP_ASYNC_16(sb + ASM_QH        + so, qhi + gq);
        CP_ASYNC_16(sb + ASM_QH + 8192 + so, qhi + gq + 64);
        CP_ASYNC_16(sb + ASM_QL        + so, qlo + gq);
        CP_ASYNC_16(sb + ASM_QL + 8192 + so, qlo + gq + 64);
    }
    CP_ASYNC_COMMIT();

    float o[16][4];
    #pragma unroll
    for (int nt = 0; nt < 16; nt++)
        #pragma unroll
        for (int j = 0; j < 4; j++) o[nt][j] = 0.f;
    float m0 = -1e30f, m1 = -1e30f, lsum0 = 0.f, lsum1 = 0.f;

    for (int kt = 0; kt <= qb; kt++) {
        const int k0 = kt << 6;
        // K tile (single fp16, own group)
        #pragma unroll
        for (int i = 0; i < 4; i++) {
            const int r = r0 + i * 16;
            const uint32_t so = SMEM_SWIZZLE_128B((uint32_t)(r * 128 + c16 * 16));
            const size_t gk = hbase + (size_t)(k0 + r) * 128 + c16 * 8;
            CP_ASYNC_16(sb + ASM_KH        + so, khi + gk);
            CP_ASYNC_16(sb + ASM_KH + 8192 + so, khi + gk + 64);
        }
        CP_ASYNC_COMMIT();
        // V tile (single fp16, separate group — lands during S + softmax)
        #pragma unroll
        for (int i = 0; i < 8; i++) {
            const int d = r0 + i * 16;
            const uint32_t so = SMEM_SWIZZLE_128B((uint32_t)(d * 128 + c16 * 16));
            const size_t gv = vbase + (size_t)d * LSEQ + k0 + c16 * 8;
            CP_ASYNC_16(sb + ASM_VH + so, vhit + gv);
        }
        CP_ASYNC_COMMIT();
        CP_ASYNC_WAIT_1();
        __syncthreads();

        // S = Q K^T (2-pass fp16)
        float s[8][4];
        #pragma unroll
        for (int nb = 0; nb < 8; nb++)
            #pragma unroll
            for (int j = 0; j < 4; j++) s[nb][j] = 0.f;

        #pragma unroll
        for (int ks = 0; ks < 8; ks++) {
            const uint32_t qtH = sb + ASM_QH + (ks >> 2) * 8192;
            const uint32_t qtL = sb + ASM_QL + (ks >> 2) * 8192;
            const uint32_t ktt = sb + ASM_KH + (ks >> 2) * 8192;
            const uint32_t kb = (ks & 3) * 32;
            uint32_t ah[4], al[4];
            const uint32_t aoff = SMEM_SWIZZLE_128B(
                (uint32_t)((wid * 16 + a_row) * 128 + kb + a_kb));
            LDSM_X4(ah[0], ah[1], ah[2], ah[3], qtH + aoff);
            LDSM_X4(al[0], al[1], al[2], al[3], qtL + aoff);
            #pragma unroll
            for (int ng = 0; ng < 4; ng++) {
                const uint32_t boff = SMEM_SWIZZLE_128B(
                    (uint32_t)((ng * 16 + b_row) * 128 + kb + b_kb));
                uint32_t k0r, k1r, k2r, k3r;
                LDSM_X4(k0r, k1r, k2r, k3r, ktt + boff);
                uint32_t bh0[2] = {k0r, k1r}, bh1[2] = {k2r, k3r};
                MMA_F16(s[ng * 2],     ah, bh0);
                MMA_F16(s[ng * 2 + 1], ah, bh1);
                MMA_F16(s[ng * 2],     al, bh0);
                MMA_F16(s[ng * 2 + 1], al, bh1);
            }
        }

        if (kt == qb) {
            const int qr = wid * 16 + g;
            #pragma unroll
            for (int nb = 0; nb < 8; nb++) {
                const int col = nb * 8 + t2;
                if (col     > qr)     s[nb][0] = -1e30f;
                if (col + 1 > qr)     s[nb][1] = -1e30f;
                if (col     > qr + 8) s[nb][2] = -1e30f;
                if (col + 1 > qr + 8) s[nb][3] = -1e30f;
            }
        }

        float mx0 = -1e30f, mx1 = -1e30f;
        #pragma unroll
        for (int nb = 0; nb < 8; nb++) {
            mx0 = fmaxf(mx0, fmaxf(s[nb][0], s[nb][1]));
            mx1 = fmaxf(mx1, fmaxf(s[nb][2], s[nb][3]));
        }
        mx0 = fmaxf(mx0, __shfl_xor_sync(0xffffffffu, mx0, 1));
        mx0 = fmaxf(mx0, __shfl_xor_sync(0xffffffffu, mx0, 2));
        mx1 = fmaxf(mx1, __shfl_xor_sync(0xffffffffu, mx1, 1));
        mx1 = fmaxf(mx1, __shfl_xor_sync(0xffffffffu, mx1, 2));
        const float mn0 = fmaxf(m0, mx0), mn1 = fmaxf(m1, mx1);
        const float al0 = __expf(m0 - mn0), al1 = __expf(m1 - mn1);
        m0 = mn0; m1 = mn1;

        float rs0 = 0.f, rs1 = 0.f;
        uint32_t pHg[8], pHg8[8], pLg[8], pLg8[8];
        #pragma unroll
        for (int nb = 0; nb < 8; nb++) {
            float p0 = __expf(s[nb][0] - mn0), p1 = __expf(s[nb][1] - mn0);
            float p2 = __expf(s[nb][2] - mn1), p3 = __expf(s[nb][3] - mn1);
            rs0 += p0 + p1; rs1 += p2 + p3;
            __half h0 = __float2half_rn(p0), h1 = __float2half_rn(p1);
            __half h2 = __float2half_rn(p2), h3 = __float2half_rn(p3);
            pHg[nb]  = pack_h2(h0, h1);
            pHg8[nb] = pack_h2(h2, h3);
            pLg[nb]  = pack_h2(__float2half_rn(p0 - __half2float(h0)),
                               __float2half_rn(p1 - __half2float(h1)));
            pLg8[nb] = pack_h2(__float2half_rn(p2 - __half2float(h2)),
                               __float2half_rn(p3 - __half2float(h3)));
        }
        rs0 += __shfl_xor_sync(0xffffffffu, rs0, 1);
        rs0 += __shfl_xor_sync(0xffffffffu, rs0, 2);
        rs1 += __shfl_xor_sync(0xffffffffu, rs1, 1);
        rs1 += __shfl_xor_sync(0xffffffffu, rs1, 2);
        lsum0 = lsum0 * al0 + rs0;
        lsum1 = lsum1 * al1 + rs1;
        #pragma unroll
        for (int nt = 0; nt < 16; nt++) {
            o[nt][0] *= al0; o[nt][1] *= al0;
            o[nt][2] *= al1; o[nt][3] *= al1;
        }

        CP_ASYNC_WAIT_0();      // V complete
        __syncthreads();

        // O += P V (2-pass fp16)
        #pragma unroll
        for (int kn = 0; kn < 4; kn++) {
            uint32_t aH[4] = {pHg[2 * kn], pHg8[2 * kn], pHg[2 * kn + 1], pHg8[2 * kn + 1]};
            uint32_t aL[4] = {pLg[2 * kn], pLg8[2 * kn], pLg[2 * kn + 1], pLg8[2 * kn + 1]};
            #pragma unroll
            for (int ng = 0; ng < 8; ng++) {
                const uint32_t boff = SMEM_SWIZZLE_128B(
                    (uint32_t)((ng * 16 + b_row) * 128 + kn * 32 + b_kb));
                uint32_t v0r, v1r, v2r, v3r;
                LDSM_X4(v0r, v1r, v2r, v3r, sb + ASM_VH + boff);
                uint32_t vh0[2] = {v0r, v1r}, vh1[2] = {v2r, v3r};
                MMA_F16(o[ng * 2],     aH, vh0);
                MMA_F16(o[ng * 2 + 1], aH, vh1);
                MMA_F16(o[ng * 2],     aL, vh0);
                MMA_F16(o[ng * 2 + 1], aL, vh1);
            }
        }
        __syncthreads();
    }

    // epilogue: normalize, sigmoid(gate), split to fp16 hi/lo
    const float inv0 = 1.0f / lsum0;
    const float inv1 = 1.0f / lsum1;
    const int qr0 = q0 + wid * 16 + g;
    const int qr1 = qr0 + 8;
    const size_t prow0 = (tokbase + qr0) * PW + 6144 + h * 128;
    const size_t prow1 = (tokbase + qr1) * PW + 6144 + h * 128;
    const size_t arow0 = (tokbase + qr0) * HIDN + h * 128;
    const size_t arow1 = (tokbase + qr1) * HIDN + h * 128;
    #pragma unroll
    for (int nb = 0; nb < 16; nb++) {
        const int d = nb * 8 + t2;
        float2 g0 = *(const float2*)&proj[prow0 + d];
        float2 g1 = *(const float2*)&proj[prow1 + d];
        g0.x = 1.0f / (1.0f + __expf(-g0.x));
        g0.y = 1.0f / (1.0f + __expf(-g0.y));
        g1.x = 1.0f / (1.0f + __expf(-g1.x));
        g1.y = 1.0f / (1.0f + __expf(-g1.y));
        float x0 = o[nb][0] * inv0 * g0.x;
        float x1 = o[nb][1] * inv0 * g0.y;
        float x2 = o[nb][2] * inv1 * g1.x;
        float x3 = o[nb][3] * inv1 * g1.y;
        __half hh0 = __float2half_rn(x0), hh1 = __float2half_rn(x1);
        __half hh2 = __float2half_rn(x2), hh3 = __float2half_rn(x3);
        *(uint32_t*)&att_hi[arow0 + d] = pack_h2(hh0, hh1);
        *(uint32_t*)&att_hi[arow1 + d] = pack_h2(hh2, hh3);
        *(uint32_t*)&att_lo[arow0 + d] = pack_h2(
            __float2half_rn(x0 - __half2float(hh0)),
            __float2half_rn(x1 - __half2float(hh1)));
        *(uint32_t*)&att_lo[arow1 + d] = pack_h2(
            __float2half_rn(x2 - __half2float(hh2)),
            __float2half_rn(x3 - __half2float(hh3)));
    }
}

// ---------------------------------------------------------------------------
extern "C" void kernel_launch(void* const* d_in, const int* in_sizes, int n_in,
                              void* d_out, int out_size)
{
    const float* hs    = (const float*)d_in[0];   // (4,2048,2048)
    const float* wqkvg = (const float*)d_in[1];   // (2048,8192)
    const float* wout  = (const float*)d_in[2];   // (2048,2048)
    float* out = (float*)d_out;

    float* proj; float *ropec, *ropes;
    __half *hs_hi, *hs_lo, *wq_hi, *wo_hi, *at_hi, *at_lo;
    __half *q_hi, *q_lo, *k_hi, *v_hi;
    cudaGetSymbolAddress((void**)&proj,  g_proj);
    cudaGetSymbolAddress((void**)&ropec, g_ropec);
    cudaGetSymbolAddress((void**)&ropes, g_ropes);
    cudaGetSymbolAddress((void**)&hs_hi, g_hs_hi);
    cudaGetSymbolAddress((void**)&hs_lo, g_hs_lo);
    cudaGetSymbolAddress((void**)&wq_hi, g_wq_hi);
    cudaGetSymbolAddress((void**)&wo_hi, g_wo_hi);
    cudaGetSymbolAddress((void**)&at_hi, g_at_hi);
    cudaGetSymbolAddress((void**)&at_lo, g_at_lo);
    cudaGetSymbolAddress((void**)&q_hi,  g_q_hi);
    cudaGetSymbolAddress((void**)&q_lo,  g_q_lo);
    cudaGetSymbolAddress((void**)&k_hi,  g_k_hi);
    cudaGetSymbolAddress((void**)&v_hi,  g_v_hi);

    cudaFuncSetAttribute(gemm_f16x2, cudaFuncAttributeMaxDynamicSharedMemorySize, GSM_TOTAL);
    cudaFuncSetAttribute(attn_hmma,  cudaFuncAttributeMaxDynamicSharedMemorySize, ATTN_SMEM);

    // 0) RoPE table + fp16 splits + weight transposes
    rope_kernel<<<LSEQ, 64>>>(ropec, ropes);
    split_kernel<<<(TOK * HIDN / 4 + 255) / 256, 256>>>(hs, hs_hi, hs_lo, TOK * HIDN / 4);
    tsplit_kernel<<<dim3(PW / 32,   HIDN / 32), 256>>>(wqkvg, wq_hi, HIDN, PW);
    tsplit_kernel<<<dim3(HIDN / 32, HIDN / 32), 256>>>(wout,  wo_hi, HIDN, HIDN);

    // 1) QKVG projection (fp16 2-pass; gate columns [6144,8192) use 1 pass)
    gemm_f16x2<<<dim3(PW / 128, TOK / 128), 256, GSM_TOTAL>>>(
        hs_hi, hs_lo, wq_hi, proj, TOK, PW, HIDN, 6144);

    // 2) RMSNorm + RoPE -> q fp16 2-split, k fp16 single
    postproc<<<TOK, 256>>>(proj, ropec, ropes, q_hi, q_lo, k_hi);

    // 2b) V transpose -> single fp16
    vsplit<<<dim3(LSEQ / 64, 4, 64), 256>>>(proj, v_hi);

    // 3) fp16 2-pass causal flash attention (64 KB smem, 3 CTAs/SM)
    attn_hmma<<<dim3(32, 64), 128, ATTN_SMEM>>>(
        q_hi, q_lo, k_hi, v_hi, proj, at_hi, at_lo);

    // 4) output projection (fp16 2-pass everywhere)
    gemm_f16x2<<<dim3(HIDN / 128, TOK / 128), 256, GSM_TOTAL>>>(
        at_hi, at_lo, wo_hi, out, TOK, HIDN, HIDN, HIDN);
}